// round 7
// baseline (speedup 1.0000x reference)
#include <cuda_runtime.h>
#include <cstdint>

#define FULLMASK 0xffffffffu
#define NMAX 100000
#define BP4 130   // float4 pitch; 130 mod 8 = 2 -> 8-lane phases hit distinct 16B banks

static __device__ float g_sum_i[NMAX];
static __device__ float g_sum_j[NMAX];
static __device__ float g_cnt_i[NMAX];
static __device__ float g_cnt_j[NMAX];

__device__ __forceinline__ uint32_t to_tf32(float f) {
    uint32_t r;
    asm("cvt.rna.tf32.f32 %0, %1;" : "=r"(r) : "f"(f));
    return r;
}
__device__ __forceinline__ float silu_t(float z) {
    float zh = 0.5f * z, t;
    asm("tanh.approx.f32 %0, %1;" : "=f"(t) : "f"(zh));
    return fmaf(zh, t, zh);   // z*sigmoid(z) = zh*(1+tanh(zh)); 1 MUFU
}
__device__ __forceinline__ void mma_tf32(float* d, const uint32_t* a,
                                         uint32_t b0, uint32_t b1) {
    asm volatile(
        "mma.sync.aligned.m16n8k8.row.col.f32.tf32.tf32.f32 "
        "{%0,%1,%2,%3}, {%4,%5,%6,%7}, {%8,%9}, {%0,%1,%2,%3};"
        : "+f"(d[0]), "+f"(d[1]), "+f"(d[2]), "+f"(d[3])
        : "r"(a[0]), "r"(a[1]), "r"(a[2]), "r"(a[3]), "r"(b0), "r"(b1));
}

__global__ void zero_kernel(int n) {
    int t = blockIdx.x * blockDim.x + threadIdx.x;
    if (t < n) {
        g_sum_i[t] = 0.f; g_sum_j[t] = 0.f;
        g_cnt_i[t] = 0.f; g_cnt_j[t] = 0.f;
    }
}
__global__ void dummy_kernel() {}   // launch-slot padding so ncu (#4) hits edge_kernel
__global__ void finalize_kernel(float* __restrict__ out, int n) {
    int t = blockIdx.x * blockDim.x + threadIdx.x;
    if (t < n) {
        out[t] = g_sum_i[t] / fmaxf(g_cnt_i[t], 1.f)
               + g_sum_j[t] / fmaxf(g_cnt_j[t], 1.f);
    }
}

// Task = 16 edges x 2 dirs = two m16 tiles, handled by a WARP PAIR that splits
// the n-dimension (64 output cols each) -> acc halves to 64 regs -> 12 warps/SM.
__global__ void __launch_bounds__(384, 1)
edge_kernel(const float* __restrict__ v,
            const float* __restrict__ r_ij,
            const float* __restrict__ W0,
            const float* __restrict__ b0,
            const float* __restrict__ W1,
            const float* __restrict__ b1,
            const float* __restrict__ W2,
            const float* __restrict__ b2,
            const int* __restrict__ ei0,
            const int* __restrict__ ei1,
            int E) {
    extern __shared__ float4 Bq[];           // [32][BP4]
    __shared__ float4 W0s4[128];
    __shared__ float  b0s[128];
    __shared__ float2 s_bw[128];             // (b1, W2)

    const int tid = threadIdx.x;

    // Bq[(k2*4+m)*BP4 + n] = (W1T[16k2+m][n], [+4], [+8], [+12]);  W1T[k][n]=W1[n*128+k]
    for (int idx = tid; idx < 32 * 128; idx += blockDim.x) {
        int rb = idx >> 7, n = idx & 127;
        int k2 = rb >> 2, mm = rb & 3;
        int r0 = 16 * k2 + mm;
        Bq[rb * BP4 + n] = make_float4(
            __uint_as_float(to_tf32(W1[n * 128 + r0])),
            __uint_as_float(to_tf32(W1[n * 128 + r0 + 4])),
            __uint_as_float(to_tf32(W1[n * 128 + r0 + 8])),
            __uint_as_float(to_tf32(W1[n * 128 + r0 + 12])));
    }
    if (tid < 128) {
        W0s4[tid] = ((const float4*)W0)[tid];
        b0s[tid]  = b0[tid];
        s_bw[tid] = make_float2(b1[tid], W2[tid]);
    }
    __syncthreads();

    const int lane = tid & 31;
    const int wid  = tid >> 5;
    const int nh   = wid & 1;     // n-half: 0 -> cols 0-63, 1 -> cols 64-127
    const int m    = lane & 3;    // frag col group
    const int q    = lane >> 2;   // frag row group (rows q, q+8)
    const int el0  = lane >> 3;   // edge slot of row q within a tile
    const int dir  = q & 1;       // row = 2*edge + dir
    const float sgn = dir ? -1.f : 1.f;
    const float b2v = b2[0];

    const int gp = blockIdx.x * 6 + (wid >> 1);   // global pair id
    const int np = gridDim.x * 6;
    const int ntask = (E + 15) >> 4;

    for (int task = gp; task < ntask; task += np) {
        const int base = task << 4;

        // lanes 0-15 gather 16 edges; count atomics only from nh==0 warp
        int ii = 0, jj = 0;
        float rr = 0.f, dx = 0.f, dy = 0.f, dz = 0.f;
        if (lane < 16) {
            int e = base + lane;
            bool valid = e < E;
            int ec = valid ? e : E - 1;
            ii = ei0[ec]; jj = ei1[ec];
            float a0 = r_ij[3 * ec], a1 = r_ij[3 * ec + 1], a2 = r_ij[3 * ec + 2];
            rr = sqrtf(a0 * a0 + a1 * a1 + a2 * a2) * (1.0f / 3.0f);   // /H, H=3
            dx = v[3 * ii]     - v[3 * jj];
            dy = v[3 * ii + 1] - v[3 * jj + 1];
            dz = v[3 * ii + 2] - v[3 * jj + 2];
            if (valid && nh == 0) {
                atomicAdd(&g_cnt_i[ii], 1.f);
                atomicAdd(&g_cnt_j[jj], 1.f);
            }
        }
        // broadcasts: s = 2*tile + rowhalf; source edge = 8*tile + 4*rowhalf + el0
        float rrb[4], vxb[4], vyb[4], vzb[4];
        int iib[4], jjb[4];
#pragma unroll
        for (int s = 0; s < 4; s++) {
            int src = ((s >> 1) << 3) + ((s & 1) << 2) + el0;
            rrb[s] = __shfl_sync(FULLMASK, rr, src);
            vxb[s] = __shfl_sync(FULLMASK, dx, src) * sgn;
            vyb[s] = __shfl_sync(FULLMASK, dy, src) * sgn;
            vzb[s] = __shfl_sync(FULLMASK, dz, src) * sgn;
            iib[s] = __shfl_sync(FULLMASK, ii, src);
            jjb[s] = __shfl_sync(FULLMASK, jj, src);
        }

        float acc[16][4];   // [tile*8 + u][frag], u = n-tile within this warp's half
#pragma unroll
        for (int n = 0; n < 16; n++)
            acc[n][0] = acc[n][1] = acc[n][2] = acc[n][3] = 0.f;

#pragma unroll
        for (int k2 = 0; k2 < 8; k2++) {
            // layer 0 -> A frags for k-steps 2*k2 (p=0) and 2*k2+1 (p=1)
            uint32_t af[2][2][4];   // [tile][p][frag]
#pragma unroll
            for (int h = 0; h < 4; h++) {
                int p = h >> 1, ch = h & 1;
                int c = 16 * k2 + m + 8 * p + 4 * ch;
                float4 w = W0s4[c];
                float bb = b0s[c];
#pragma unroll
                for (int s = 0; s < 4; s++) {
                    float z = fmaf(w.x, rrb[s], bb)
                            + fmaf(w.y, vxb[s], fmaf(w.z, vyb[s], w.w * vzb[s]));
                    af[s >> 1][p][2 * ch + (s & 1)] = to_tf32(silu_t(z));
                }
            }
            const float4* bp = Bq + (k2 * 4 + m) * BP4 + q + 64 * nh;
            float4 bq[8];
#pragma unroll
            for (int u = 0; u < 8; u++) bq[u] = bp[8 * u];
#pragma unroll
            for (int p = 0; p < 2; p++) {
#pragma unroll
                for (int u = 0; u < 8; u++) {
                    uint32_t bb0 = __float_as_uint(p ? bq[u].z : bq[u].x);
                    uint32_t bb1 = __float_as_uint(p ? bq[u].w : bq[u].y);
                    mma_tf32(acc[u],     af[0][p], bb0, bb1);
                    mma_tf32(acc[8 + u], af[1][p], bb0, bb1);
                }
            }
        }

        // epilogue: partial sum over this warp's 64 cols; both halves atomicAdd
#pragma unroll
        for (int t = 0; t < 2; t++) {
            float p0 = 0.f, p1 = 0.f;
#pragma unroll
            for (int u = 0; u < 8; u++) {
                int c0 = 8 * (8 * nh + u) + 2 * m;
                float2 bw0 = s_bw[c0];
                float2 bw1 = s_bw[c0 + 1];
                const float* a = acc[8 * t + u];
                p0 += silu_t(a[0] + bw0.x) * bw0.y + silu_t(a[1] + bw1.x) * bw1.y;
                p1 += silu_t(a[2] + bw0.x) * bw0.y + silu_t(a[3] + bw1.x) * bw1.y;
            }
            p0 += __shfl_xor_sync(FULLMASK, p0, 1);
            p0 += __shfl_xor_sync(FULLMASK, p0, 2);
            p1 += __shfl_xor_sync(FULLMASK, p1, 1);
            p1 += __shfl_xor_sync(FULLMASK, p1, 2);
            if (m == 0) {
                int s0 = 2 * t, s1 = 2 * t + 1;
                int e0 = base + 8 * t + el0;
                float bias = nh ? 0.f : b2v;   // add b2 exactly once per row
                if (e0 < E) {
                    float val = p0 + bias;
                    if (dir == 0) atomicAdd(&g_sum_i[iib[s0]], val);
                    else          atomicAdd(&g_sum_j[jjb[s0]], val);
                }
                if (e0 + 4 < E) {
                    float val = p1 + bias;
                    if (dir == 0) atomicAdd(&g_sum_i[iib[s1]], val);
                    else          atomicAdd(&g_sum_j[jjb[s1]], val);
                }
            }
        }
    }
}

extern "C" void kernel_launch(void* const* d_in, const int* in_sizes, int n_in,
                              void* d_out, int out_size) {
    const float* v   = (const float*)d_in[0];
    const float* rij = (const float*)d_in[1];
    const float* W0  = (const float*)d_in[2];
    const float* b0  = (const float*)d_in[3];
    const float* W1  = (const float*)d_in[4];
    const float* b1  = (const float*)d_in[5];
    const float* W2  = (const float*)d_in[6];
    const float* b2  = (const float*)d_in[7];
    const int*   ei  = (const int*)d_in[8];   // int32 on device (JAX x64 off)

    const int E = in_sizes[8] / 2;            // edge_index is [2,E]
    const int N = out_size;
    float* out = (float*)d_out;

    const int DSMEM = 32 * BP4 * 16;          // 66560 B
    cudaFuncSetAttribute(edge_kernel,
                         cudaFuncAttributeMaxDynamicSharedMemorySize, DSMEM);

    int nb = (N + 255) / 256;
    zero_kernel<<<nb, 256>>>(N);
    dummy_kernel<<<1, 32>>>();   // pad launch slots: edge_kernel stays launch #4
    dummy_kernel<<<1, 32>>>();
    edge_kernel<<<148, 384, DSMEM>>>(v, rij, W0, b0, W1, b1, W2, b2,
                                     ei, ei + E, E);
    finalize_kernel<<<nb, 256>>>(out, N);
}

// round 8
// speedup vs baseline: 1.6723x; 1.6723x over previous
#include <cuda_runtime.h>
#include <cstdint>

#define FULLMASK 0xffffffffu
#define NMAX 100000
#define BPH 132   // uint2 pitch; m-stride 1056B -> banks 8m+2q, conflict-free LDS.64

static __device__ float g_sum_i[NMAX];
static __device__ float g_sum_j[NMAX];
static __device__ float g_cnt_i[NMAX];
static __device__ float g_cnt_j[NMAX];

__device__ __forceinline__ uint32_t packh2(float lo, float hi) {
    uint32_t d;   // d.lo = f16(lo), d.hi = f16(hi)
    asm("cvt.rn.f16x2.f32 %0, %1, %2;" : "=r"(d) : "f"(hi), "f"(lo));
    return d;
}
__device__ __forceinline__ float silu_t(float z) {
    float zh = 0.5f * z, t;
    asm("tanh.approx.f32 %0, %1;" : "=f"(t) : "f"(zh));
    return fmaf(zh, t, zh);   // z*sigmoid(z) = zh*(1+tanh(zh)); 1 MUFU
}
__device__ __forceinline__ void mma_f16(float* d, const uint32_t* a,
                                        uint32_t b0, uint32_t b1) {
    asm volatile(
        "mma.sync.aligned.m16n8k16.row.col.f32.f16.f16.f32 "
        "{%0,%1,%2,%3}, {%4,%5,%6,%7}, {%8,%9}, {%0,%1,%2,%3};"
        : "+f"(d[0]), "+f"(d[1]), "+f"(d[2]), "+f"(d[3])
        : "r"(a[0]), "r"(a[1]), "r"(a[2]), "r"(a[3]), "r"(b0), "r"(b1));
}

__global__ void zero_kernel(int n) {
    int t = blockIdx.x * blockDim.x + threadIdx.x;
    if (t < n) {
        g_sum_i[t] = 0.f; g_sum_j[t] = 0.f;
        g_cnt_i[t] = 0.f; g_cnt_j[t] = 0.f;
    }
}
__global__ void dummy_kernel() {}   // launch-slot padding so ncu (#4) hits edge_kernel
__global__ void finalize_kernel(float* __restrict__ out, int n) {
    int t = blockIdx.x * blockDim.x + threadIdx.x;
    if (t < n) {
        out[t] = g_sum_i[t] / fmaxf(g_cnt_i[t], 1.f)
               + g_sum_j[t] / fmaxf(g_cnt_j[t], 1.f);
    }
}

// Warp-task: 8 edges x 2 dirs = one m16 tile; n=128, k=128 via f16 m16n8k16.
// acc[16][4] = 64 regs -> <=128 regs total -> 2 CTAs/SM = 16 warps/SM.
__global__ void __launch_bounds__(256, 2)
edge_kernel(const float* __restrict__ v,
            const float* __restrict__ r_ij,
            const float* __restrict__ W0,
            const float* __restrict__ b0,
            const float* __restrict__ W1,
            const float* __restrict__ b1,
            const float* __restrict__ W2,
            const float* __restrict__ b2,
            const int* __restrict__ ei0,
            const int* __restrict__ ei1,
            int E) {
    extern __shared__ uint2 Bh[];            // [32][BPH]
    __shared__ float4 W0s4[128];
    __shared__ float  b0s[128];
    __shared__ float2 s_bw[128];             // (b1, W2)

    const int tid = threadIdx.x;

    // Bh[(k16*4+mm)*BPH + n] = { h2(W1T[k0][n], W1T[k0+1][n]),
    //                            h2(W1T[k0+8][n], W1T[k0+9][n]) }, k0=16*k16+2*mm
    for (int idx = tid; idx < 32 * 128; idx += 256) {
        int rb = idx >> 7, n = idx & 127;
        int k0 = ((rb >> 2) << 4) + ((rb & 3) << 1);
        const float* wn = W1 + n * 128;
        Bh[rb * BPH + n] = make_uint2(packh2(wn[k0],     wn[k0 + 1]),
                                      packh2(wn[k0 + 8], wn[k0 + 9]));
    }
    if (tid < 128) {
        W0s4[tid] = ((const float4*)W0)[tid];
        b0s[tid]  = b0[tid];
        s_bw[tid] = make_float2(b1[tid], W2[tid]);
    }
    __syncthreads();

    const int lane = tid & 31;
    const int m    = lane & 3;    // thread-in-group
    const int q    = lane >> 2;   // group id (rows q, q+8)
    const int el0  = lane >> 3;   // edge slot of row q; row q+8 -> el0+4
    const int dir  = q & 1;       // row = 2*edge + dir
    const float sgn = dir ? -1.f : 1.f;
    const float b2v = b2[0];

    const int gw = (blockIdx.x << 3) + (tid >> 5);
    const int nw = gridDim.x << 3;
    const int ntask = (E + 7) >> 3;

    for (int task = gw; task < ntask; task += nw) {
        const int base = task << 3;

        // lanes 0-7 gather 8 edges + fused count scatter
        int ii = 0, jj = 0;
        float rr = 0.f, dx = 0.f, dy = 0.f, dz = 0.f;
        if (lane < 8) {
            int e = base + lane;
            bool valid = e < E;
            int ec = valid ? e : E - 1;
            ii = ei0[ec]; jj = ei1[ec];
            float a0 = r_ij[3 * ec], a1 = r_ij[3 * ec + 1], a2 = r_ij[3 * ec + 2];
            rr = sqrtf(a0 * a0 + a1 * a1 + a2 * a2) * (1.0f / 3.0f);   // /H, H=3
            dx = v[3 * ii]     - v[3 * jj];
            dy = v[3 * ii + 1] - v[3 * jj + 1];
            dz = v[3 * ii + 2] - v[3 * jj + 2];
            if (valid) {
                atomicAdd(&g_cnt_i[ii], 1.f);
                atomicAdd(&g_cnt_j[jj], 1.f);
            }
        }
        // broadcasts: s = rowhalf (0 -> row q / edge el0, 1 -> row q+8 / el0+4)
        float rrb[2], vxb[2], vyb[2], vzb[2];
        int iib[2], jjb[2];
#pragma unroll
        for (int s = 0; s < 2; s++) {
            int src = el0 + 4 * s;
            rrb[s] = __shfl_sync(FULLMASK, rr, src);
            vxb[s] = __shfl_sync(FULLMASK, dx, src) * sgn;
            vyb[s] = __shfl_sync(FULLMASK, dy, src) * sgn;
            vzb[s] = __shfl_sync(FULLMASK, dz, src) * sgn;
            iib[s] = __shfl_sync(FULLMASK, ii, src);
            jjb[s] = __shfl_sync(FULLMASK, jj, src);
        }

        float acc[16][4];
#pragma unroll
        for (int n = 0; n < 16; n++)
            acc[n][0] = acc[n][1] = acc[n][2] = acc[n][3] = 0.f;

#pragma unroll
        for (int k16 = 0; k16 < 8; k16++) {
            // layer 0 -> A frags: cols 16*k16 + {2m,2m+1} (cp=0), {2m+8,2m+9} (cp=1)
            uint32_t af[4];
#pragma unroll
            for (int cp = 0; cp < 2; cp++) {
                int c = 16 * k16 + 2 * m + 8 * cp;
                float4 wA = W0s4[c];
                float4 wB = W0s4[c + 1];
                float bA = b0s[c], bB = b0s[c + 1];
#pragma unroll
                for (int s = 0; s < 2; s++) {
                    float zA = fmaf(wA.x, rrb[s], bA)
                             + fmaf(wA.y, vxb[s], fmaf(wA.z, vyb[s], wA.w * vzb[s]));
                    float zB = fmaf(wB.x, rrb[s], bB)
                             + fmaf(wB.y, vxb[s], fmaf(wB.z, vyb[s], wB.w * vzb[s]));
                    af[s + 2 * cp] = packh2(silu_t(zA), silu_t(zB));
                }
            }
            const uint2* bp = Bh + ((k16 << 2) + m) * BPH + q;
#pragma unroll
            for (int nh = 0; nh < 2; nh++) {
                uint2 bq[8];
#pragma unroll
                for (int u = 0; u < 8; u++) bq[u] = bp[8 * (8 * nh + u)];
#pragma unroll
                for (int u = 0; u < 8; u++)
                    mma_f16(acc[8 * nh + u], af, bq[u].x, bq[u].y);
            }
        }

        // epilogue: sum_c silu(h2+b1[c])*W2[c], quad-reduce, scatter
        float p0 = 0.f, p1 = 0.f;
#pragma unroll
        for (int n = 0; n < 16; n++) {
            int c0 = 8 * n + 2 * m;
            float2 bw0 = s_bw[c0];
            float2 bw1 = s_bw[c0 + 1];
            const float* a = acc[n];
            p0 += silu_t(a[0] + bw0.x) * bw0.y + silu_t(a[1] + bw1.x) * bw1.y;
            p1 += silu_t(a[2] + bw0.x) * bw0.y + silu_t(a[3] + bw1.x) * bw1.y;
        }
        p0 += __shfl_xor_sync(FULLMASK, p0, 1);
        p0 += __shfl_xor_sync(FULLMASK, p0, 2);
        p1 += __shfl_xor_sync(FULLMASK, p1, 1);
        p1 += __shfl_xor_sync(FULLMASK, p1, 2);
        if (m == 0) {
            if (base + el0 < E) {
                float val = p0 + b2v;
                if (dir == 0) atomicAdd(&g_sum_i[iib[0]], val);
                else          atomicAdd(&g_sum_j[jjb[0]], val);
            }
            if (base + el0 + 4 < E) {
                float val = p1 + b2v;
                if (dir == 0) atomicAdd(&g_sum_i[iib[1]], val);
                else          atomicAdd(&g_sum_j[jjb[1]], val);
            }
        }
    }
}

extern "C" void kernel_launch(void* const* d_in, const int* in_sizes, int n_in,
                              void* d_out, int out_size) {
    const float* v   = (const float*)d_in[0];
    const float* rij = (const float*)d_in[1];
    const float* W0  = (const float*)d_in[2];
    const float* b0  = (const float*)d_in[3];
    const float* W1  = (const float*)d_in[4];
    const float* b1  = (const float*)d_in[5];
    const float* W2  = (const float*)d_in[6];
    const float* b2  = (const float*)d_in[7];
    const int*   ei  = (const int*)d_in[8];   // int32 on device (JAX x64 off)

    const int E = in_sizes[8] / 2;            // edge_index is [2,E]
    const int N = out_size;
    float* out = (float*)d_out;

    const int DSMEM = 32 * BPH * 8;           // 33792 B
    cudaFuncSetAttribute(edge_kernel,
                         cudaFuncAttributeMaxDynamicSharedMemorySize, DSMEM);

    int nb = (N + 255) / 256;
    zero_kernel<<<nb, 256>>>(N);
    dummy_kernel<<<1, 32>>>();   // pad launch slots: edge_kernel stays launch #4
    dummy_kernel<<<1, 32>>>();
    edge_kernel<<<296, 256, DSMEM>>>(v, rij, W0, b0, W1, b1, W2, b2,
                                     ei, ei + E, E);
    finalize_kernel<<<nb, 256>>>(out, N);
}